// round 4
// baseline (speedup 1.0000x reference)
#include <cuda_runtime.h>
#include <math.h>
#include <stdint.h>

// ---------------------------------------------------------------------------
// InternLM2-7B decode-step: qkv GEMM + RoPE + paged KV fill + flash-decode
// attention + output GEMM.  All fp32.  HBM-bound (~1.24 GB/call).
// R3: attention rebuilt — cp.async double-buffered K tiles, lane-per-position
// scores from XOR-swizzled smem (no per-position shfl), per-tile rescale,
// 8-deep V load unroll.  Splits 32 -> 8.
// ---------------------------------------------------------------------------

#define B_       32
#define DMODEL   4096
#define H_       32
#define KVH      8
#define HD_      128
#define GQ       4            // H_/KVH
#define NBLK_    64           // blocks per sequence
#define QKV_N    6144         // (H + 2*KV) * HD
#define SPLITS   8            // split-K for GEMMs
#define KSPLIT   512          // DMODEL / SPLITS
#define ASPLIT   8            // attention splits per (b,kvh)
#define TPOS     32           // positions per tile
#define NTILE    16           // 512 / 32 tiles per CTA
#define SCALE_   0.08838834764831843f   // 1/sqrt(128)

// ------------------------- scratch (static, no allocs) ----------------------
__device__ float g_part[SPLITS * B_ * QKV_N];            // gemm partials (reused)
__device__ float g_q   [B_ * H_ * HD_];                  // rope'd Q
__device__ float g_attn[B_ * H_ * HD_];                  // attention output
__device__ float g_acc [B_ * KVH * ASPLIT * GQ * HD_];   // split partial accum
__device__ float g_m   [B_ * KVH * ASPLIT];              // split running max
__device__ float g_l   [B_ * KVH * ASPLIT * GQ];         // split running sum

// ---------------------------------------------------------------------------
// GEMM partial: P[split][32][N] = A[32, k0:k0+KSPLIT] @ W[k0:k0+KSPLIT, :N]
// A row-stride is DMODEL for both uses.  A==nullptr means "use g_attn".
// Inner loop: smem broadcast LDS.128 + packed fma.rn.f32x2 (FFMA2).
// ---------------------------------------------------------------------------
__global__ void gemm_partial_k(const float* __restrict__ A,
                               const float* __restrict__ W, int N)
{
    __shared__ __align__(16) float sA[128 * 36];   // [c][b] padded (stride 36)
    const float* Abase = (A == nullptr) ? g_attn : A;

    const int col = blockIdx.x * 128 + threadIdx.x;
    const int k0  = blockIdx.y * KSPLIT;

    unsigned long long acc[16];                    // 16 x f32x2 = 32 batch rows
#pragma unroll
    for (int i = 0; i < 16; i++) acc[i] = 0ull;

    for (int kt = k0; kt < k0 + KSPLIT; kt += 128) {
        const float* Ap = Abase + kt + threadIdx.x;
#pragma unroll
        for (int b = 0; b < 32; b++)
            sA[threadIdx.x * 36 + b] = Ap[b * DMODEL];
        __syncthreads();

        const float* Wp = W + (size_t)kt * N + col;
#pragma unroll 4
        for (int c = 0; c < 128; c++) {
            float w = Wp[(size_t)c * N];
            unsigned long long wp;
            asm("mov.b64 %0, {%1,%2};" : "=l"(wp) : "f"(w), "f"(w));
            const uint4* ar = (const uint4*)(sA + c * 36);
#pragma unroll
            for (int i = 0; i < 8; i++) {
                uint4 a4 = ar[i];
                unsigned long long p0, p1;
                asm("mov.b64 %0, {%1,%2};" : "=l"(p0) : "r"(a4.x), "r"(a4.y));
                asm("mov.b64 %0, {%1,%2};" : "=l"(p1) : "r"(a4.z), "r"(a4.w));
                asm("fma.rn.f32x2 %0, %1, %2, %0;" : "+l"(acc[2*i])   : "l"(p0), "l"(wp));
                asm("fma.rn.f32x2 %0, %1, %2, %0;" : "+l"(acc[2*i+1]) : "l"(p1), "l"(wp));
            }
        }
        __syncthreads();
    }

    float* out = g_part + ((size_t)blockIdx.y * 32) * N + col;
#pragma unroll
    for (int i = 0; i < 16; i++) {
        float lo, hi;
        asm("mov.b64 {%0,%1}, %2;" : "=f"(lo), "=f"(hi) : "l"(acc[i]));
        out[(size_t)(2 * i)     * N] = lo;
        out[(size_t)(2 * i + 1) * N] = hi;
    }
}

// ---------------------------------------------------------------------------
// Reduce qkv partials, apply RoPE to q & k, write q to g_q, scatter k/v into
// the paged caches.  grid (48 heads, 32 batch), 128 threads (one per dim).
// ---------------------------------------------------------------------------
__global__ void qkv_finish_k(const int* __restrict__ pos_ids,
                             const int* __restrict__ btab,
                             const int* __restrict__ seqlens,
                             float* __restrict__ kc, float* __restrict__ vc)
{
    const int hh = blockIdx.x;        // 0..31 q heads | 32..39 k | 40..47 v
    const int b  = blockIdx.y;
    const int d  = threadIdx.x;
    const int col = hh * 128 + d;

    float v = 0.f;
#pragma unroll
    for (int s = 0; s < SPLITS; s++)
        v += g_part[(size_t)(s * 32 + b) * QKV_N + col];

    float r = v;
    __shared__ float sv[128];
    if (hh < 40) {                      // q and k get RoPE
        sv[d] = v;
        __syncthreads();
        const int i = d & 63;
        const int pos = pos_ids[b];
        double invf = pow(1.0e6, -(double)(2 * i) / 128.0);
        double ang  = (double)pos * invf;
        double sd, cd;
        sincos(ang, &sd, &cd);
        const float cf = (float)cd, sf = (float)sd;
        const float x1 = sv[i], x2 = sv[i + 64];
        r = (d < 64) ? (x1 * cf - x2 * sf) : (x2 * cf + x1 * sf);
    }

    if (hh < 32) {
        g_q[(size_t)b * 4096 + col] = r;
    } else {
        const int kvh = (hh - 32) & 7;
        const int pos = seqlens[b] - 1;
        const int phys = btab[b * NBLK_ + (pos >> 6)];
        const size_t idx = (((size_t)phys * 64 + (pos & 63)) * 8 + kvh) * 128 + d;
        if (hh < 40) kc[idx] = r; else vc[idx] = r;
    }
}

// ---------------------------------------------------------------------------
// Attention partial (tiled flash-decode).
// grid (8 splits, 8 kvheads, 32 batch), 128 threads.
// Tile = 32 positions.  K staged via cp.async double buffer with XOR-swizzled
// float4 layout; scores computed lane-per-position (no shfl); block-wide tile
// max; accumulators rescaled once per tile; V loaded directly from gmem.
// ---------------------------------------------------------------------------
__device__ __forceinline__ void fma4(float4& a, float e, const float4 v) {
    a.x = fmaf(e, v.x, a.x); a.y = fmaf(e, v.y, a.y);
    a.z = fmaf(e, v.z, a.z); a.w = fmaf(e, v.w, a.w);
}
__device__ __forceinline__ void mul4(float4& a, float c) {
    a.x *= c; a.y *= c; a.z *= c; a.w *= c;
}
__device__ __forceinline__ void add4(float4& a, const float4 v) {
    a.x += v.x; a.y += v.y; a.z += v.z; a.w += v.w;
}

__device__ __forceinline__ void load_k_tile(const float* __restrict__ kc, int kvh,
                                            const int* sBT, int tileBase,
                                            float4* dst, int t)
{
#pragma unroll
    for (int i = 0; i < 8; i++) {
        const int idx  = t + i * 128;
        const int posl = idx >> 5;         // 0..31 within tile
        const int d4   = idx & 31;
        const int p    = tileBase + posl;  // 0..511 within split
        const int phys = sBT[p >> 6];
        const float* src = kc + (((size_t)phys * 64 + (p & 63)) * 8 + kvh) * 128 + d4 * 4;
        unsigned saddr = (unsigned)__cvta_generic_to_shared(dst + posl * 32 + (d4 ^ posl));
        asm volatile("cp.async.cg.shared.global [%0], [%1], 16;" :: "r"(saddr), "l"(src));
    }
    asm volatile("cp.async.commit_group;");
}

__global__ void __launch_bounds__(128) attn_partial_k(
        const float* __restrict__ kcache,
        const float* __restrict__ vcache,
        const int* __restrict__ btab,
        const int* __restrict__ seqlens)
{
    __shared__ __align__(16) float4 sK[2][TPOS * 32];   // 2 x 16KB, XOR swizzled
    __shared__ __align__(16) float4 sQ4[GQ * 32];       // 2KB
    __shared__ __align__(16) float4 sE4[TPOS];          // e per pos, 4 heads
    __shared__ __align__(16) float4 sAcc4[3 * 32 * 4];  // 6KB cross-warp reduce
    __shared__ float sRed[4];
    __shared__ int   sBT[ASPLIT];

    const int split = blockIdx.x, kvh = blockIdx.y, b = blockIdx.z;
    const int t = threadIdx.x, w = t >> 5, lane = t & 31;
    const int kvlen = seqlens[b];
    const int base  = split * 512;

    if (t < 128) sQ4[t] = ((const float4*)(g_q + (size_t)b * 4096 + kvh * 512))[t];
    if (t < ASPLIT) sBT[t] = btab[b * NBLK_ + split * ASPLIT + t];
    __syncthreads();

    load_k_tile(kcache, kvh, sBT, 0, sK[0], t);   // prologue: tile 0

    float m = -1e30f;
    float lp = 0.f;                                  // partial l for (pos-slot, head=w)
    float4 a0 = {0,0,0,0}, a1 = a0, a2 = a0, a3 = a0; // V accum: dim4=lane, heads 0..3
    int buf = 0;

    for (int tt = 0; tt < NTILE; tt++) {
        if (tt < NTILE - 1)
            load_k_tile(kcache, kvh, sBT, (tt + 1) * TPOS, sK[buf ^ 1], t);
        if (tt < NTILE - 1) asm volatile("cp.async.wait_group 1;");
        else                asm volatile("cp.async.wait_group 0;");
        __syncthreads();

        // ---- scores: head h = w, position p = lane ----
        const float4* kp = sK[buf] + lane * 32;
        const float4* qp = sQ4 + w * 32;
        float s = 0.f;
#pragma unroll
        for (int d4 = 0; d4 < 32; d4++) {
            const float4 k4 = kp[d4 ^ lane];
            const float4 q4 = qp[d4];
            s = fmaf(k4.x, q4.x, s); s = fmaf(k4.y, q4.y, s);
            s = fmaf(k4.z, q4.z, s); s = fmaf(k4.w, q4.w, s);
        }
        s *= SCALE_;
        const int gp = base + tt * TPOS + lane;
        if (gp >= kvlen) s = -1e30f;

        // ---- block-wide joint max over (4 heads x 32 pos) ----
        float wm = s;
#pragma unroll
        for (int off = 16; off > 0; off >>= 1)
            wm = fmaxf(wm, __shfl_xor_sync(0xffffffffu, wm, off));
        if (lane == 0) sRed[w] = wm;
        __syncthreads();
        const float tmax = fmaxf(fmaxf(sRed[0], sRed[1]), fmaxf(sRed[2], sRed[3]));
        const float mnew = fmaxf(m, tmax);
        const float corr = __expf(m - mnew);
        m = mnew;

        const float e = __expf(s - mnew);
        lp = lp * corr + e;
        ((float*)sE4)[lane * 4 + w] = e;

        // rescale accumulators once per tile
        mul4(a0, corr); mul4(a1, corr); mul4(a2, corr); mul4(a3, corr);
        __syncthreads();   // sE ready

        // ---- V accumulation: dim4 = lane, warp w covers positions 8w..8w+7 ----
#pragma unroll
        for (int j = 0; j < 8; j++) {
            const int posl = w * 8 + j;
            const int p    = tt * TPOS + posl;           // 0..511 within split
            const int phys = sBT[p >> 6];
            const float4 v4 = *(const float4*)(vcache +
                (((size_t)phys * 64 + (p & 63)) * 8 + kvh) * 128 + lane * 4);
            const float4 e4 = sE4[posl];
            fma4(a0, e4.x, v4); fma4(a1, e4.y, v4);
            fma4(a2, e4.z, v4); fma4(a3, e4.w, v4);
        }
        __syncthreads();   // protect sE/sRed before next tile
        buf ^= 1;
    }

    // ---- epilogue ----
    const int pk = b * KVH + kvh;
    const int sidx = pk * ASPLIT + split;

    // l: sum lp over the warp's 32 position-slots (head = w)
#pragma unroll
    for (int off = 16; off > 0; off >>= 1)
        lp += __shfl_xor_sync(0xffffffffu, lp, off);
    if (lane == 0) g_l[sidx * 4 + w] = lp;
    if (t == 0)    g_m[sidx] = m;

    // V accumulators: reduce across the 4 warps (position subsets)
    if (w > 0) {
        sAcc4[(w - 1) * 128 + lane * 4 + 0] = a0;
        sAcc4[(w - 1) * 128 + lane * 4 + 1] = a1;
        sAcc4[(w - 1) * 128 + lane * 4 + 2] = a2;
        sAcc4[(w - 1) * 128 + lane * 4 + 3] = a3;
    }
    __syncthreads();
    if (w == 0) {
#pragma unroll
        for (int ww = 0; ww < 3; ww++) {
            add4(a0, sAcc4[ww * 128 + lane * 4 + 0]);
            add4(a1, sAcc4[ww * 128 + lane * 4 + 1]);
            add4(a2, sAcc4[ww * 128 + lane * 4 + 2]);
            add4(a3, sAcc4[ww * 128 + lane * 4 + 3]);
        }
        float4* op = (float4*)g_acc + (size_t)sidx * GQ * 32;
        op[0 * 32 + lane] = a0;
        op[1 * 32 + lane] = a1;
        op[2 * 32 + lane] = a2;
        op[3 * 32 + lane] = a3;
    }
}

// ---------------------------------------------------------------------------
// Combine the 8 split partials per (b, head).  grid (B*H), 128 threads.
// ---------------------------------------------------------------------------
__global__ void attn_combine_k()
{
    const int bh = blockIdx.x;            // 0..1023
    const int b = bh >> 5, h = bh & 31;
    const int kvh = h >> 2, g = h & 3;
    const int pk = b * KVH + kvh;
    const int d = threadIdx.x;

    __shared__ float sm[ASPLIT], sl[ASPLIT];
    if (d < ASPLIT) {
        sm[d] = g_m[pk * ASPLIT + d];
        sl[d] = g_l[(pk * ASPLIT + d) * 4 + g];
    }
    __syncthreads();

    float gm = -1e30f;
#pragma unroll
    for (int s = 0; s < ASPLIT; s++) gm = fmaxf(gm, sm[s]);

    float num = 0.f, den = 0.f;
    const float* accp = g_acc + (size_t)pk * ASPLIT * GQ * HD_ + g * HD_ + d;
#pragma unroll
    for (int s = 0; s < ASPLIT; s++) {
        const float wgt = __expf(sm[s] - gm);
        den += wgt * sl[s];
        num += wgt * accp[(size_t)s * (GQ * HD_)];
    }
    g_attn[(size_t)b * 4096 + h * HD_ + d] = num / den;
}

// ---------------------------------------------------------------------------
// Reduce wo partials into d_out.  grid (32 colblocks, 32 batch).
// ---------------------------------------------------------------------------
__global__ void wo_finish_k(float* __restrict__ out)
{
    const int b = blockIdx.y;
    const int col = blockIdx.x * 128 + threadIdx.x;
    float v = 0.f;
#pragma unroll
    for (int s = 0; s < SPLITS; s++)
        v += g_part[(size_t)(s * 32 + b) * DMODEL + col];
    out[(size_t)b * DMODEL + col] = v;
}

// ---------------------------------------------------------------------------
extern "C" void kernel_launch(void* const* d_in, const int* in_sizes, int n_in,
                              void* d_out, int out_size)
{
    const float* hidden  = (const float*)d_in[0];
    const float* wqkv    = (const float*)d_in[1];
    const float* wo      = (const float*)d_in[2];
    float*       kcache  = (float*)d_in[3];   // mutated in place (idempotent)
    float*       vcache  = (float*)d_in[4];
    const int*   pos_ids = (const int*)d_in[5];
    const int*   btab    = (const int*)d_in[6];
    const int*   seqlens = (const int*)d_in[7];
    float*       out     = (float*)d_out;

    // 1) qkv = hidden @ wqkv  (split-K partials)
    gemm_partial_k<<<dim3(QKV_N / 128, SPLITS), 128>>>(hidden, wqkv, QKV_N);
    // 2) reduce + RoPE + KV-cache fill + stage q
    qkv_finish_k<<<dim3(48, 32), 128>>>(pos_ids, btab, seqlens, kcache, vcache);
    // 3) tiled flash-decode split partials over the paged cache
    attn_partial_k<<<dim3(ASPLIT, KVH, B_), 128>>>(kcache, vcache, btab, seqlens);
    // 4) combine splits -> g_attn
    attn_combine_k<<<B_ * H_, 128>>>();
    // 5) out = g_attn @ wo  (split-K partials; A==nullptr selects g_attn)
    gemm_partial_k<<<dim3(DMODEL / 128, SPLITS), 128>>>(nullptr, wo, DMODEL);
    // 6) reduce partials into d_out
    wo_finish_k<<<dim3(32, 32), 128>>>(out);
}